// round 3
// baseline (speedup 1.0000x reference)
#include <cuda_runtime.h>

// DynamicKVCache update: out = [concat(cache_k, key, dim=1), concat(cache_v, value, dim=1)]
// Shapes: cache [8, 4096, 32, 128] f32, new [8, 1, 32, 128] f32.
// Pure streaming copy, HBM-bound (R2: 88.2% DRAM, 7.0 TB/s).
// Per-batch output = 4,195,328 float4 = 4097 chunks of 1024 float4.
// Chunks 0..4095 from cache, chunk 4096 from appended key/value (uniform
// per-block branch). 128-thread blocks, 8 independent float4 per thread
// (MLP_p1=8, 128B/thread) with evict-first (.cs) hints.

static constexpr long long CACHE_F4  = 4096LL * 4096 / 4;    // 4,194,304
static constexpr long long NEW_F4    = 4096LL / 4;           // 1,024
static constexpr long long BATCH_F4  = CACHE_F4 + NEW_F4;    // 4,195,328 = 4097 * 1024
static constexpr long long TENSOR_F4 = 8LL * BATCH_F4;
static constexpr int THREADS   = 128;
static constexpr int PER_TH    = 8;                          // float4 per thread
static constexpr int CHUNK_F4  = THREADS * PER_TH;           // 1024
static constexpr int BLOCKS_X  = (int)(BATCH_F4 / CHUNK_F4); // 4097, exact
static constexpr int CACHE_CHUNKS = (int)(CACHE_F4 / CHUNK_F4); // 4096

__global__ __launch_bounds__(THREADS)
void kvcache_concat_kernel(const float4* __restrict__ cache_k,
                           const float4* __restrict__ cache_v,
                           const float4* __restrict__ key,
                           const float4* __restrict__ value,
                           float4* __restrict__ out)
{
    const int chunk = blockIdx.x;    // [0, 4097)
    const int b     = blockIdx.y;    // batch
    const int t     = blockIdx.z;    // 0 = k, 1 = v

    const long long out_base = (long long)t * TENSOR_F4
                             + (long long)b * BATCH_F4
                             + (long long)chunk * CHUNK_F4;

    const float4* __restrict__ src;
    if (chunk < CACHE_CHUNKS) {
        const float4* __restrict__ cache = t ? cache_v : cache_k;
        src = cache + (long long)b * CACHE_F4 + (long long)chunk * CHUNK_F4;
    } else {
        const float4* __restrict__ nw = t ? value : key;
        src = nw + (long long)b * NEW_F4;
    }

    const int tid = threadIdx.x;

    // 8 independent coalesced 16B loads issued back-to-back (MLP_p1=8),
    // then 8 stores. All traffic is touch-once -> evict-first hints.
    float4 v[PER_TH];
#pragma unroll
    for (int j = 0; j < PER_TH; j++)
        v[j] = __ldcs(src + tid + j * THREADS);
#pragma unroll
    for (int j = 0; j < PER_TH; j++)
        __stcs(out + out_base + tid + j * THREADS, v[j]);
}

extern "C" void kernel_launch(void* const* d_in, const int* in_sizes, int n_in,
                              void* d_out, int out_size)
{
    const float4* cache_k = (const float4*)d_in[0];
    const float4* cache_v = (const float4*)d_in[1];
    const float4* key     = (const float4*)d_in[2];
    const float4* value   = (const float4*)d_in[3];
    float4* out = (float4*)d_out;

    dim3 grid(BLOCKS_X, 8, 2);
    kvcache_concat_kernel<<<grid, THREADS>>>(cache_k, cache_v, key, value, out);
}

// round 4
// speedup vs baseline: 1.0002x; 1.0002x over previous
#include <cuda_runtime.h>

// DynamicKVCache update: out = [concat(cache_k, key, dim=1), concat(cache_v, value, dim=1)]
// Shapes: cache [8, 4096, 32, 128] f32, new [8, 1, 32, 128] f32.
// Pure streaming copy, HBM-bound. Best measured operating point (R2):
// 256-thread blocks, 4 independent float4 per thread (MLP_p1=4), evict-first
// hints, chunk = 1024 float4. Per-batch output = 4097 chunks; chunks 0..4095
// come from the cache, chunk 4096 from the appended key/value (uniform
// per-block branch, no per-thread divergence).
// Measured: 299.4us kernel, 7.0 TB/s = 87.4% of HBM spec (ceiling).

static constexpr long long CACHE_F4  = 4096LL * 4096 / 4;    // 4,194,304
static constexpr long long NEW_F4    = 4096LL / 4;           // 1,024
static constexpr long long BATCH_F4  = CACHE_F4 + NEW_F4;    // 4,195,328 = 4097 * 1024
static constexpr long long TENSOR_F4 = 8LL * BATCH_F4;
static constexpr int THREADS   = 256;
static constexpr int PER_TH    = 4;                          // float4 per thread
static constexpr int CHUNK_F4  = THREADS * PER_TH;           // 1024
static constexpr int BLOCKS_X  = (int)(BATCH_F4 / CHUNK_F4); // 4097, exact
static constexpr int CACHE_CHUNKS = (int)(CACHE_F4 / CHUNK_F4); // 4096

__global__ __launch_bounds__(THREADS)
void kvcache_concat_kernel(const float4* __restrict__ cache_k,
                           const float4* __restrict__ cache_v,
                           const float4* __restrict__ key,
                           const float4* __restrict__ value,
                           float4* __restrict__ out)
{
    const int chunk = blockIdx.x;    // [0, 4097)
    const int b     = blockIdx.y;    // batch
    const int t     = blockIdx.z;    // 0 = k, 1 = v

    const long long out_base = (long long)t * TENSOR_F4
                             + (long long)b * BATCH_F4
                             + (long long)chunk * CHUNK_F4;

    // Branch-free tensor select, then uniform per-block source branch.
    const float4* __restrict__ cache = t ? cache_v : cache_k;
    const float4* __restrict__ nw    = t ? value   : key;

    const float4* __restrict__ src =
        (chunk < CACHE_CHUNKS)
            ? cache + (long long)b * CACHE_F4 + (long long)chunk * CHUNK_F4
            : nw    + (long long)b * NEW_F4;

    const int tid = threadIdx.x;

    // 4 independent coalesced 16B loads issued back-to-back (MLP_p1=4),
    // then 4 full-line stores. Touch-once traffic -> evict-first hints.
    float4 v0 = __ldcs(src + tid);
    float4 v1 = __ldcs(src + tid + THREADS);
    float4 v2 = __ldcs(src + tid + 2 * THREADS);
    float4 v3 = __ldcs(src + tid + 3 * THREADS);
    __stcs(out + out_base + tid,               v0);
    __stcs(out + out_base + tid +     THREADS, v1);
    __stcs(out + out_base + tid + 2 * THREADS, v2);
    __stcs(out + out_base + tid + 3 * THREADS, v3);
}

extern "C" void kernel_launch(void* const* d_in, const int* in_sizes, int n_in,
                              void* d_out, int out_size)
{
    const float4* cache_k = (const float4*)d_in[0];
    const float4* cache_v = (const float4*)d_in[1];
    const float4* key     = (const float4*)d_in[2];
    const float4* value   = (const float4*)d_in[3];
    float4* out = (float4*)d_out;

    dim3 grid(BLOCKS_X, 8, 2);
    kvcache_concat_kernel<<<grid, THREADS>>>(cache_k, cache_v, key, value, out);
}

// round 5
// speedup vs baseline: 1.0029x; 1.0027x over previous
#include <cuda_runtime.h>

// DynamicKVCache update: out = [concat(cache_k, key, dim=1), concat(cache_v, value, dim=1)]
// Shapes: cache [8, 4096, 32, 128] f32, new [8, 1, 32, 128] f32.
// Pure streaming copy, HBM-bound (88.2% DRAM, 7.0 TB/s at R2 config).
// This round: coarser chunks — 256 threads x 8 float4 (chunk = 2048 f4 = 32KB)
// to double read-burst/write-burst granularity per block (fewer DRAM R/W
// turnarounds). Cache region = 2048 full chunks per batch (exact); appended
// key/value slot = one half-chunk tail per batch (uniform per-block path,
// threads do 4 of 8 iterations).

static constexpr long long CACHE_F4  = 4096LL * 4096 / 4;    // 4,194,304
static constexpr long long NEW_F4    = 4096LL / 4;           // 1,024
static constexpr long long BATCH_F4  = CACHE_F4 + NEW_F4;    // 4,195,328
static constexpr long long TENSOR_F4 = 8LL * BATCH_F4;
static constexpr int THREADS   = 256;
static constexpr int PER_TH    = 8;                          // float4 per thread (full chunk)
static constexpr int CHUNK_F4  = THREADS * PER_TH;           // 2048
static constexpr int CACHE_CHUNKS = (int)(CACHE_F4 / CHUNK_F4); // 2048, exact
static constexpr int BLOCKS_X  = CACHE_CHUNKS + 1;           // +1 tail (new slot, 1024 f4)

__global__ __launch_bounds__(THREADS)
void kvcache_concat_kernel(const float4* __restrict__ cache_k,
                           const float4* __restrict__ cache_v,
                           const float4* __restrict__ key,
                           const float4* __restrict__ value,
                           float4* __restrict__ out)
{
    const int chunk = blockIdx.x;    // [0, 2049)
    const int b     = blockIdx.y;    // batch
    const int t     = blockIdx.z;    // 0 = k, 1 = v

    const long long out_base = (long long)t * TENSOR_F4
                             + (long long)b * BATCH_F4
                             + (long long)chunk * CHUNK_F4;
    const int tid = threadIdx.x;

    const float4* __restrict__ cache = t ? cache_v : cache_k;
    const float4* __restrict__ nw    = t ? value   : key;

    if (chunk < CACHE_CHUNKS) {
        // Full 32KB chunk: 8 independent coalesced LDG.128, then 8 STG.128.
        const float4* __restrict__ src =
            cache + (long long)b * CACHE_F4 + (long long)chunk * CHUNK_F4;
        float4 v[PER_TH];
#pragma unroll
        for (int j = 0; j < PER_TH; j++)
            v[j] = __ldcs(src + tid + j * THREADS);
#pragma unroll
        for (int j = 0; j < PER_TH; j++)
            __stcs(out + out_base + tid + j * THREADS, v[j]);
    } else {
        // Appended slot: 1024 float4 (half chunk), uniform per-block path.
        const float4* __restrict__ src = nw + (long long)b * NEW_F4;
        float4 v[4];
#pragma unroll
        for (int j = 0; j < 4; j++)
            v[j] = __ldcs(src + tid + j * THREADS);
#pragma unroll
        for (int j = 0; j < 4; j++)
            __stcs(out + out_base + tid + j * THREADS, v[j]);
    }
}

extern "C" void kernel_launch(void* const* d_in, const int* in_sizes, int n_in,
                              void* d_out, int out_size)
{
    const float4* cache_k = (const float4*)d_in[0];
    const float4* cache_v = (const float4*)d_in[1];
    const float4* key     = (const float4*)d_in[2];
    const float4* value   = (const float4*)d_in[3];
    float4* out = (float4*)d_out;

    dim3 grid(BLOCKS_X, 8, 2);
    kvcache_concat_kernel<<<grid, THREADS>>>(cache_k, cache_v, key, value, out);
}

// round 6
// speedup vs baseline: 1.0046x; 1.0017x over previous
#include <cuda_runtime.h>

// DynamicKVCache update: out = [concat(cache_k, key, dim=1), concat(cache_v, value, dim=1)]
// Shapes: cache [8, 4096, 32, 128] f32, new [8, 1, 32, 128] f32.
//
// FINAL: pure streaming copy pinned at the B300 HBM mixed-stream ceiling.
// Measured 88.2% DRAM-active / ~7.0 TB/s across MLP{4,8}, occ{60-80%},
// chunk{16,32KB} — invariant, so the bound is DRAM R/W turnaround, not the
// kernel. Config: 256 threads x 8 float4 (32KB chunk), evict-first (.cs)
// loads+stores, uniform per-block branch for the appended slot (half chunk).
// Cache region = 2048 exact chunks/batch; grid = (2049, 8 batch, 2 tensors).

static constexpr long long CACHE_F4  = 4096LL * 4096 / 4;    // 4,194,304
static constexpr long long NEW_F4    = 4096LL / 4;           // 1,024
static constexpr long long BATCH_F4  = CACHE_F4 + NEW_F4;    // 4,195,328
static constexpr long long TENSOR_F4 = 8LL * BATCH_F4;
static constexpr int THREADS   = 256;
static constexpr int PER_TH    = 8;                          // float4 per thread (full chunk)
static constexpr int CHUNK_F4  = THREADS * PER_TH;           // 2048
static constexpr int CACHE_CHUNKS = (int)(CACHE_F4 / CHUNK_F4); // 2048, exact
static constexpr int BLOCKS_X  = CACHE_CHUNKS + 1;           // +1 tail (new slot, 1024 f4)

__global__ __launch_bounds__(THREADS)
void kvcache_concat_kernel(const float4* __restrict__ cache_k,
                           const float4* __restrict__ cache_v,
                           const float4* __restrict__ key,
                           const float4* __restrict__ value,
                           float4* __restrict__ out)
{
    const int chunk = blockIdx.x;    // [0, 2049)
    const int b     = blockIdx.y;    // batch
    const int t     = blockIdx.z;    // 0 = k, 1 = v

    const long long out_base = (long long)t * TENSOR_F4
                             + (long long)b * BATCH_F4
                             + (long long)chunk * CHUNK_F4;
    const int tid = threadIdx.x;

    const float4* __restrict__ cache = t ? cache_v : cache_k;
    const float4* __restrict__ nw    = t ? value   : key;

    if (chunk < CACHE_CHUNKS) {
        // Full 32KB chunk: 8 independent coalesced LDG.128, then 8 STG.128.
        const float4* __restrict__ src =
            cache + (long long)b * CACHE_F4 + (long long)chunk * CHUNK_F4;
        float4 v[PER_TH];
#pragma unroll
        for (int j = 0; j < PER_TH; j++)
            v[j] = __ldcs(src + tid + j * THREADS);
#pragma unroll
        for (int j = 0; j < PER_TH; j++)
            __stcs(out + out_base + tid + j * THREADS, v[j]);
    } else {
        // Appended slot: 1024 float4 (half chunk), uniform per-block path.
        const float4* __restrict__ src = nw + (long long)b * NEW_F4;
        float4 v[4];
#pragma unroll
        for (int j = 0; j < 4; j++)
            v[j] = __ldcs(src + tid + j * THREADS);
#pragma unroll
        for (int j = 0; j < 4; j++)
            __stcs(out + out_base + tid + j * THREADS, v[j]);
    }
}

extern "C" void kernel_launch(void* const* d_in, const int* in_sizes, int n_in,
                              void* d_out, int out_size)
{
    const float4* cache_k = (const float4*)d_in[0];
    const float4* cache_v = (const float4*)d_in[1];
    const float4* key     = (const float4*)d_in[2];
    const float4* value   = (const float4*)d_in[3];
    float4* out = (float4*)d_out;

    dim3 grid(BLOCKS_X, 8, 2);
    kvcache_concat_kernel<<<grid, THREADS>>>(cache_k, cache_v, key, value, out);
}